// round 3
// baseline (speedup 1.0000x reference)
#include <cuda_runtime.h>
#include <cuda_bf16.h>

#define NN 100000
#define NE 1600000
#define HH 128
#define GG 256
#define SCAN_BLK 1024
#define SCAN_NB ((NN + SCAN_BLK - 1) / SCAN_BLK)   // 98

// ---------------- scratch (static device globals; no allocation) ----------------
__device__ int   g_deg[NN];
__device__ int   g_fill[NN];
__device__ int   g_rowptr[NN + 1];
__device__ int   g_csr_src[NE];
__device__ int   g_bsums[SCAN_NB];
__device__ int   g_gcnt[GG];
__device__ int   g_goff[GG + 1];
__device__ float g_dinv[NN];
__device__ float g_s[(size_t)NN * HH];   // pre-scaled features (input to aggregate)
__device__ float g_h[(size_t)NN * HH];   // layer output

// ---------------- zero counters ----------------
__global__ void k_zero() {
    int i = blockIdx.x * blockDim.x + threadIdx.x;
    if (i < NN) { g_deg[i] = 0; g_fill[i] = 0; }
    if (i < GG) g_gcnt[i] = 0;
}

// ---------------- degree histogram (by dst) + graph-size histogram ----------------
__global__ void k_hist(const int* __restrict__ dst, const int* __restrict__ bids) {
    int i = blockIdx.x * blockDim.x + threadIdx.x;
    if (i < NE) atomicAdd(&g_deg[dst[i]], 1);
    if (i < NN) atomicAdd(&g_gcnt[bids[i]], 1);
}

// ---------------- scan pass 1 (also computes dinv = rsqrt(deg+1)) ----------------
__global__ void k_scan1() {
    __shared__ int sm[SCAN_BLK];
    int t = threadIdx.x;
    int i = blockIdx.x * SCAN_BLK + t;
    int v = (i < NN) ? g_deg[i] : 0;
    if (i < NN) g_dinv[i] = rsqrtf((float)(v + 1));
    sm[t] = v;
    __syncthreads();
    #pragma unroll
    for (int o = 1; o < SCAN_BLK; o <<= 1) {
        int add = (t >= o) ? sm[t - o] : 0;
        __syncthreads();
        sm[t] += add;
        __syncthreads();
    }
    if (i < NN) g_rowptr[i] = sm[t] - v;          // block-local exclusive
    if (t == SCAN_BLK - 1) g_bsums[blockIdx.x] = sm[t];
}

__global__ void k_scan2() {                        // 1 block, 128 threads
    __shared__ int sm[128];
    int t = threadIdx.x;
    int v = (t < SCAN_NB) ? g_bsums[t] : 0;
    sm[t] = v;
    __syncthreads();
    #pragma unroll
    for (int o = 1; o < 128; o <<= 1) {
        int add = (t >= o) ? sm[t - o] : 0;
        __syncthreads();
        sm[t] += add;
        __syncthreads();
    }
    if (t < SCAN_NB) g_bsums[t] = sm[t] - v;       // exclusive block offsets
}

__global__ void k_scan3() {
    int i = blockIdx.x * blockDim.x + threadIdx.x;
    if (i < NN) g_rowptr[i] += g_bsums[i / SCAN_BLK];
    if (i == 0) g_rowptr[NN] = NE;
}

// ---------------- graph offsets (batch_ids sorted -> contiguous ranges) ----------------
__global__ void k_goff() {                         // 1 block, 256 threads
    __shared__ int sm[GG];
    int t = threadIdx.x;
    int v = g_gcnt[t];
    sm[t] = v;
    __syncthreads();
    #pragma unroll
    for (int o = 1; o < GG; o <<= 1) {
        int add = (t >= o) ? sm[t - o] : 0;
        __syncthreads();
        sm[t] += add;
        __syncthreads();
    }
    g_goff[t] = sm[t] - v;
    if (t == GG - 1) g_goff[GG] = sm[t];
}

// ---------------- CSR fill ----------------
__global__ void k_fill(const int* __restrict__ src, const int* __restrict__ dst) {
    int e = blockIdx.x * blockDim.x + threadIdx.x;
    if (e < NE) {
        int d = dst[e];
        int base = __ldg(&g_rowptr[d]);
        int p = base + atomicAdd(&g_fill[d], 1);
        g_csr_src[p] = src[e];
    }
}

// ---------------- layer-1 transform: s = (x @ W1) * dinv ----------------
__global__ void k_sx(const float* __restrict__ x, const float* __restrict__ W1) {
    int t = blockIdx.x * blockDim.x + threadIdx.x;
    if (t >= NN * 32) return;
    int node = t >> 5;
    int j4 = (t & 31) * 4;
    float x0 = __ldg(&x[node * 2]);
    float x1 = __ldg(&x[node * 2 + 1]);
    float di = g_dinv[node];
    float4 w0 = *(const float4*)&W1[j4];           // W1[0][j..j+3]
    float4 w1 = *(const float4*)&W1[HH + j4];      // W1[1][j..j+3]
    float4 r;
    r.x = (x0 * w0.x + x1 * w1.x) * di;
    r.y = (x0 * w0.y + x1 * w1.y) * di;
    r.z = (x0 * w0.z + x1 * w1.z) * di;
    r.w = (x0 * w0.w + x1 * w1.w) * di;
    *(float4*)&g_s[(size_t)node * HH + j4] = r;
}

// ---------------- aggregate: h = relu(dinv*(s_i + sum_{src->i} s_src) + b) ----------------
// one warp per node; lane owns a float4 of the 128-wide feature row.
// Index loads batched before gathers so 4 independent LDG.128s are in flight.
__global__ void k_agg(const float* __restrict__ bias) {
    int gt = blockIdx.x * blockDim.x + threadIdx.x;
    int w = gt >> 5;
    if (w >= NN) return;
    int lane = gt & 31;
    size_t fo = (size_t)lane * 4;
    float4 acc = *(const float4*)&g_s[(size_t)w * HH + fo];
    int beg = g_rowptr[w], end = g_rowptr[w + 1];
    int e = beg;
    for (; e + 3 < end; e += 4) {
        int s0 = __ldg(&g_csr_src[e]);
        int s1 = __ldg(&g_csr_src[e + 1]);
        int s2 = __ldg(&g_csr_src[e + 2]);
        int s3 = __ldg(&g_csr_src[e + 3]);
        float4 v0 = *(const float4*)&g_s[(size_t)s0 * HH + fo];
        float4 v1 = *(const float4*)&g_s[(size_t)s1 * HH + fo];
        float4 v2 = *(const float4*)&g_s[(size_t)s2 * HH + fo];
        float4 v3 = *(const float4*)&g_s[(size_t)s3 * HH + fo];
        float ax = (v0.x + v1.x) + (v2.x + v3.x);
        float ay = (v0.y + v1.y) + (v2.y + v3.y);
        float az = (v0.z + v1.z) + (v2.z + v3.z);
        float aw = (v0.w + v1.w) + (v2.w + v3.w);
        acc.x += ax; acc.y += ay; acc.z += az; acc.w += aw;
    }
    for (; e < end; e++) {
        int s0 = __ldg(&g_csr_src[e]);
        float4 v0 = *(const float4*)&g_s[(size_t)s0 * HH + fo];
        acc.x += v0.x; acc.y += v0.y; acc.z += v0.z; acc.w += v0.w;
    }
    float di = g_dinv[w];
    float4 b = *(const float4*)&bias[fo];
    float4 o;
    o.x = fmaxf(fmaf(acc.x, di, b.x), 0.f);
    o.y = fmaxf(fmaf(acc.y, di, b.y), 0.f);
    o.z = fmaxf(fmaf(acc.z, di, b.z), 0.f);
    o.w = fmaxf(fmaf(acc.w, di, b.w), 0.f);
    *(float4*)&g_h[(size_t)w * HH + fo] = o;
}

// ---------------- layer-2 transform: s = (h @ W2) * dinv  (tiled SIMT GEMM) ----------------
#define GTR 64
__global__ void k_gemm(const float* __restrict__ W2) {
    __shared__ float sh[GTR][33];      // 64 rows x 32 k (+pad)
    __shared__ float sw[32][HH];       // 32 k x 128 cols
    int tid = threadIdx.x;             // 256 threads
    int tx = tid & 31;                 // col group: cols tx*4..tx*4+3
    int ty = tid >> 5;                 // row group: rows ty*8..ty*8+7
    int row0 = blockIdx.x * GTR;
    float4 acc[8];
    #pragma unroll
    for (int r = 0; r < 8; r++) acc[r] = make_float4(0.f, 0.f, 0.f, 0.f);

    for (int kt = 0; kt < 4; kt++) {
        for (int idx = tid; idx < GTR * 32; idx += 256) {
            int r = idx >> 5, k = idx & 31;
            int gr = row0 + r;
            sh[r][k] = (gr < NN) ? g_h[(size_t)gr * HH + kt * 32 + k] : 0.f;
        }
        for (int idx = tid; idx < 32 * HH; idx += 256) {
            int k = idx >> 7, j = idx & 127;
            sw[k][j] = W2[(kt * 32 + k) * HH + j];
        }
        __syncthreads();
        #pragma unroll 4
        for (int k = 0; k < 32; k++) {
            float4 wv = *(const float4*)&sw[k][tx * 4];
            #pragma unroll
            for (int r = 0; r < 8; r++) {
                float hv = sh[ty * 8 + r][k];
                acc[r].x = fmaf(hv, wv.x, acc[r].x);
                acc[r].y = fmaf(hv, wv.y, acc[r].y);
                acc[r].z = fmaf(hv, wv.z, acc[r].z);
                acc[r].w = fmaf(hv, wv.w, acc[r].w);
            }
        }
        __syncthreads();
    }
    #pragma unroll
    for (int r = 0; r < 8; r++) {
        int gr = row0 + ty * 8 + r;
        if (gr < NN) {
            float di = g_dinv[gr];
            float4 o;
            o.x = acc[r].x * di; o.y = acc[r].y * di;
            o.z = acc[r].z * di; o.w = acc[r].w * di;
            *(float4*)&g_s[(size_t)gr * HH + tx * 4] = o;
        }
    }
}

// ---------------- pooling + MLP head, one block per graph ----------------
__global__ void k_mlp(const float* __restrict__ fc1W, const float* __restrict__ fc1b,
                      const float* __restrict__ fc2W, const float* __restrict__ fc2b,
                      float* __restrict__ out) {
    int g = blockIdx.x;
    int t = threadIdx.x;                // 128 threads, one per feature
    __shared__ float sp[HH];
    __shared__ float sr[4];
    int beg = g_goff[g], end = g_goff[g + 1];
    float acc = 0.f;
    for (int n = beg; n < end; n++) acc += g_h[(size_t)n * HH + t];
    float cnt = (float)(end - beg);
    sp[t] = acc / fmaxf(cnt, 1.f);
    __syncthreads();
    float h = fc1b[t];
    #pragma unroll 8
    for (int k = 0; k < HH; k++) h = fmaf(sp[k], fc1W[k * HH + t], h);
    h = fmaxf(h, 0.f);
    float v = h * fc2W[t];
    #pragma unroll
    for (int o = 16; o > 0; o >>= 1) v += __shfl_down_sync(0xffffffffu, v, o);
    if ((t & 31) == 0) sr[t >> 5] = v;
    __syncthreads();
    if (t == 0) out[g] = sr[0] + sr[1] + sr[2] + sr[3] + fc2b[0];
}

// ---------------- launch ----------------
extern "C" void kernel_launch(void* const* d_in, const int* in_sizes, int n_in,
                              void* d_out, int out_size) {
    const float* x    = (const float*)d_in[0];
    const int*   esrc = (const int*)  d_in[1];
    const int*   edst = (const int*)  d_in[2];
    const int*   bids = (const int*)  d_in[3];
    int off = (n_in >= 13) ? 5 : 4;    // num_graphs may or may not be materialized
    const float* W1   = (const float*)d_in[off + 0];
    const float* b1   = (const float*)d_in[off + 1];
    const float* W2   = (const float*)d_in[off + 2];
    const float* b2   = (const float*)d_in[off + 3];
    const float* fc1W = (const float*)d_in[off + 4];
    const float* fc1b = (const float*)d_in[off + 5];
    const float* fc2W = (const float*)d_in[off + 6];
    const float* fc2b = (const float*)d_in[off + 7];
    float* out = (float*)d_out;

    int nb_n  = (NN + 255) / 256;
    int nb_e  = (NE + 255) / 256;
    int nb_nw = (NN * 32 + 255) / 256;

    // graph structure (shared by both layers)
    k_zero<<<nb_n, 256>>>();
    k_hist<<<nb_e, 256>>>(edst, bids);
    k_scan1<<<SCAN_NB, SCAN_BLK>>>();
    k_scan2<<<1, 128>>>();
    k_scan3<<<nb_n, 256>>>();
    k_goff<<<1, GG>>>();
    k_fill<<<nb_e, 256>>>(esrc, edst);

    // layer 1
    k_sx<<<nb_nw, 256>>>(x, W1);
    k_agg<<<nb_nw, 256>>>(b1);
    // layer 2
    k_gemm<<<(NN + GTR - 1) / GTR, 256>>>(W2);
    k_agg<<<nb_nw, 256>>>(b2);
    // pool + head
    k_mlp<<<GG, HH>>>(fc1W, fc1b, fc2W, fc2b, out);
}

// round 4
// speedup vs baseline: 1.1668x; 1.1668x over previous
#include <cuda_runtime.h>
#include <cuda_fp16.h>
#include <cuda_bf16.h>

#define NN 100000
#define NE 1600000
#define HH 128
#define GG 256
#define SCAN_BLK 1024
#define SCAN_NB ((NN + SCAN_BLK - 1) / SCAN_BLK)   // 98

// ---------------- scratch (static device globals; no allocation) ----------------
__device__ int    g_deg[NN];
__device__ int    g_fill[NN];          // seeded to rowptr in k_scan3
__device__ int    g_rowptr[NN + 1];
__device__ int    g_csr_src[NE];
__device__ int    g_bsums[SCAN_NB];
__device__ int    g_gcnt[GG];
__device__ int    g_goff[GG + 1];
__device__ float  g_dinv[NN];
__device__ float2 g_t[NN];                     // dinv * x  (layer-1 gather operand)
__device__ float  g_s[(size_t)NN * HH];        // fp32 scaled features (self term / gemm io)
__device__ uint2  g_s16[(size_t)NN * 32];      // fp16 copy of g_s (layer-2 gather operand)
__device__ float  g_h[(size_t)NN * HH];        // layer output

// ---------------- zero counters ----------------
__global__ void k_zero() {
    int i = blockIdx.x * blockDim.x + threadIdx.x;
    if (i < NN) g_deg[i] = 0;
    if (i < GG) g_gcnt[i] = 0;
}

// ---------------- degree histogram (by dst) + graph-size histogram ----------------
__global__ void k_hist(const int* __restrict__ dst, const int* __restrict__ bids) {
    int i = blockIdx.x * blockDim.x + threadIdx.x;
    if (i < NE) atomicAdd(&g_deg[dst[i]], 1);
    if (i < NN) atomicAdd(&g_gcnt[bids[i]], 1);
}

// ---------------- scan pass 1 (also computes dinv = rsqrt(deg+1)) ----------------
__global__ void k_scan1() {
    __shared__ int sm[SCAN_BLK];
    int t = threadIdx.x;
    int i = blockIdx.x * SCAN_BLK + t;
    int v = (i < NN) ? g_deg[i] : 0;
    if (i < NN) g_dinv[i] = rsqrtf((float)(v + 1));
    sm[t] = v;
    __syncthreads();
    #pragma unroll
    for (int o = 1; o < SCAN_BLK; o <<= 1) {
        int add = (t >= o) ? sm[t - o] : 0;
        __syncthreads();
        sm[t] += add;
        __syncthreads();
    }
    if (i < NN) g_rowptr[i] = sm[t] - v;          // block-local exclusive
    if (t == SCAN_BLK - 1) g_bsums[blockIdx.x] = sm[t];
}

__global__ void k_scan2() {                        // 1 block, 128 threads
    __shared__ int sm[128];
    int t = threadIdx.x;
    int v = (t < SCAN_NB) ? g_bsums[t] : 0;
    sm[t] = v;
    __syncthreads();
    #pragma unroll
    for (int o = 1; o < 128; o <<= 1) {
        int add = (t >= o) ? sm[t - o] : 0;
        __syncthreads();
        sm[t] += add;
        __syncthreads();
    }
    if (t < SCAN_NB) g_bsums[t] = sm[t] - v;       // exclusive block offsets
}

// scan finalize + seed fill counters + compute t = dinv * x
__global__ void k_scan3(const float* __restrict__ x) {
    int i = blockIdx.x * blockDim.x + threadIdx.x;
    if (i < NN) {
        int rp = g_rowptr[i] + g_bsums[i / SCAN_BLK];
        g_rowptr[i] = rp;
        g_fill[i] = rp;
        float di = g_dinv[i];
        float2 xv = *(const float2*)&x[i * 2];
        g_t[i] = make_float2(xv.x * di, xv.y * di);
    }
    if (i == 0) g_rowptr[NN] = NE;
}

// ---------------- graph offsets (batch_ids sorted -> contiguous ranges) ----------------
__global__ void k_goff() {                         // 1 block, 256 threads
    __shared__ int sm[GG];
    int t = threadIdx.x;
    int v = g_gcnt[t];
    sm[t] = v;
    __syncthreads();
    #pragma unroll
    for (int o = 1; o < GG; o <<= 1) {
        int add = (t >= o) ? sm[t - o] : 0;
        __syncthreads();
        sm[t] += add;
        __syncthreads();
    }
    g_goff[t] = sm[t] - v;
    if (t == GG - 1) g_goff[GG] = sm[t];
}

// ---------------- CSR fill (counter pre-seeded with rowptr) ----------------
__global__ void k_fill(const int* __restrict__ src, const int* __restrict__ dst) {
    int e = blockIdx.x * blockDim.x + threadIdx.x;
    if (e < NE) {
        int d = dst[e];
        int p = atomicAdd(&g_fill[d], 1);
        g_csr_src[p] = src[e];
    }
}

// ---------------- layer 1 fused: gather t (2 floats/edge), transform, relu ----------------
// h_i = relu( dinv_i * ( (t_i + sum_src t_src) @ W1 ) + b1 ),  t = dinv*x
// one warp per node: lanes cooperatively gather edges, butterfly-reduce,
// then each lane computes 4 of the 128 output features.
__global__ void k_agg1(const float* __restrict__ W1, const float* __restrict__ b1) {
    int gt = blockIdx.x * blockDim.x + threadIdx.x;
    int w = gt >> 5;
    if (w >= NN) return;
    int lane = gt & 31;
    int beg = g_rowptr[w], end = g_rowptr[w + 1];
    float ax = 0.f, ay = 0.f;
    for (int e = beg + lane; e < end; e += 32) {
        int s = __ldg(&g_csr_src[e]);
        float2 tv = g_t[s];
        ax += tv.x; ay += tv.y;
    }
    #pragma unroll
    for (int o = 16; o > 0; o >>= 1) {
        ax += __shfl_xor_sync(0xffffffffu, ax, o);
        ay += __shfl_xor_sync(0xffffffffu, ay, o);
    }
    float2 ts = g_t[w];
    ax += ts.x; ay += ts.y;
    float di = g_dinv[w];
    ax *= di; ay *= di;
    int j4 = lane * 4;
    float4 w0 = *(const float4*)&W1[j4];          // W1[0][j..j+3]
    float4 w1 = *(const float4*)&W1[HH + j4];     // W1[1][j..j+3]
    float4 b  = *(const float4*)&b1[j4];
    float4 o;
    o.x = fmaxf(fmaf(ax, w0.x, fmaf(ay, w1.x, b.x)), 0.f);
    o.y = fmaxf(fmaf(ax, w0.y, fmaf(ay, w1.y, b.y)), 0.f);
    o.z = fmaxf(fmaf(ax, w0.z, fmaf(ay, w1.z, b.z)), 0.f);
    o.w = fmaxf(fmaf(ax, w0.w, fmaf(ay, w1.w, b.w)), 0.f);
    *(float4*)&g_h[(size_t)w * HH + j4] = o;
}

// ---------------- layer-2 transform: s = (h @ W2) * dinv  (tiled SIMT GEMM) ----------------
// writes fp32 g_s (self term) and fp16 g_s16 (gather operand)
#define GTR 64
__global__ void k_gemm(const float* __restrict__ W2) {
    __shared__ float sh[GTR][33];      // 64 rows x 32 k (+pad)
    __shared__ float sw[32][HH];       // 32 k x 128 cols
    int tid = threadIdx.x;             // 256 threads
    int tx = tid & 31;                 // col group: cols tx*4..tx*4+3
    int ty = tid >> 5;                 // row group: rows ty*8..ty*8+7
    int row0 = blockIdx.x * GTR;
    float4 acc[8];
    #pragma unroll
    for (int r = 0; r < 8; r++) acc[r] = make_float4(0.f, 0.f, 0.f, 0.f);

    for (int kt = 0; kt < 4; kt++) {
        for (int idx = tid; idx < GTR * 32; idx += 256) {
            int r = idx >> 5, k = idx & 31;
            int gr = row0 + r;
            sh[r][k] = (gr < NN) ? g_h[(size_t)gr * HH + kt * 32 + k] : 0.f;
        }
        for (int idx = tid; idx < 32 * HH; idx += 256) {
            int k = idx >> 7, j = idx & 127;
            sw[k][j] = W2[(kt * 32 + k) * HH + j];
        }
        __syncthreads();
        #pragma unroll 4
        for (int k = 0; k < 32; k++) {
            float4 wv = *(const float4*)&sw[k][tx * 4];
            #pragma unroll
            for (int r = 0; r < 8; r++) {
                float hv = sh[ty * 8 + r][k];
                acc[r].x = fmaf(hv, wv.x, acc[r].x);
                acc[r].y = fmaf(hv, wv.y, acc[r].y);
                acc[r].z = fmaf(hv, wv.z, acc[r].z);
                acc[r].w = fmaf(hv, wv.w, acc[r].w);
            }
        }
        __syncthreads();
    }
    #pragma unroll
    for (int r = 0; r < 8; r++) {
        int gr = row0 + ty * 8 + r;
        if (gr < NN) {
            float di = g_dinv[gr];
            float4 o;
            o.x = acc[r].x * di; o.y = acc[r].y * di;
            o.z = acc[r].z * di; o.w = acc[r].w * di;
            *(float4*)&g_s[(size_t)gr * HH + tx * 4] = o;
            __half2 h0 = __floats2half2_rn(o.x, o.y);
            __half2 h1 = __floats2half2_rn(o.z, o.w);
            uint2 u;
            u.x = *(unsigned int*)&h0;
            u.y = *(unsigned int*)&h1;
            g_s16[(size_t)gr * 32 + tx] = u;
        }
    }
}

// ---------------- layer-2 aggregate: h = relu(dinv*(s_i + sum s_src) + b) ----------------
// one warp per node; lane owns 4 features. Neighbors gathered from fp16 copy
// (8B/lane = 256B/row), self term from fp32. Accumulation in fp32.
__global__ void k_agg2(const float* __restrict__ bias) {
    int gt = blockIdx.x * blockDim.x + threadIdx.x;
    int w = gt >> 5;
    if (w >= NN) return;
    int lane = gt & 31;
    float4 acc = *(const float4*)&g_s[(size_t)w * HH + lane * 4];
    int beg = g_rowptr[w], end = g_rowptr[w + 1];
    int e = beg;
    for (; e + 3 < end; e += 4) {
        int s0 = __ldg(&g_csr_src[e]);
        int s1 = __ldg(&g_csr_src[e + 1]);
        int s2 = __ldg(&g_csr_src[e + 2]);
        int s3 = __ldg(&g_csr_src[e + 3]);
        uint2 u0 = g_s16[(size_t)s0 * 32 + lane];
        uint2 u1 = g_s16[(size_t)s1 * 32 + lane];
        uint2 u2 = g_s16[(size_t)s2 * 32 + lane];
        uint2 u3 = g_s16[(size_t)s3 * 32 + lane];
        float2 a0 = __half22float2(*(__half2*)&u0.x), b0 = __half22float2(*(__half2*)&u0.y);
        float2 a1 = __half22float2(*(__half2*)&u1.x), b1v = __half22float2(*(__half2*)&u1.y);
        float2 a2 = __half22float2(*(__half2*)&u2.x), b2v = __half22float2(*(__half2*)&u2.y);
        float2 a3 = __half22float2(*(__half2*)&u3.x), b3v = __half22float2(*(__half2*)&u3.y);
        acc.x += (a0.x + a1.x) + (a2.x + a3.x);
        acc.y += (a0.y + a1.y) + (a2.y + a3.y);
        acc.z += (b0.x + b1v.x) + (b2v.x + b3v.x);
        acc.w += (b0.y + b1v.y) + (b2v.y + b3v.y);
    }
    for (; e < end; e++) {
        int s0 = __ldg(&g_csr_src[e]);
        uint2 u0 = g_s16[(size_t)s0 * 32 + lane];
        float2 a0 = __half22float2(*(__half2*)&u0.x), b0 = __half22float2(*(__half2*)&u0.y);
        acc.x += a0.x; acc.y += a0.y; acc.z += b0.x; acc.w += b0.y;
    }
    float di = g_dinv[w];
    float4 b = *(const float4*)&bias[lane * 4];
    float4 o;
    o.x = fmaxf(fmaf(acc.x, di, b.x), 0.f);
    o.y = fmaxf(fmaf(acc.y, di, b.y), 0.f);
    o.z = fmaxf(fmaf(acc.z, di, b.z), 0.f);
    o.w = fmaxf(fmaf(acc.w, di, b.w), 0.f);
    *(float4*)&g_h[(size_t)w * HH + lane * 4] = o;
}

// ---------------- pooling + MLP head, one block per graph ----------------
__global__ void k_mlp(const float* __restrict__ fc1W, const float* __restrict__ fc1b,
                      const float* __restrict__ fc2W, const float* __restrict__ fc2b,
                      float* __restrict__ out) {
    int g = blockIdx.x;
    int t = threadIdx.x;                // 128 threads, one per feature
    __shared__ float sp[HH];
    __shared__ float sr[4];
    int beg = g_goff[g], end = g_goff[g + 1];
    float acc = 0.f;
    for (int n = beg; n < end; n++) acc += g_h[(size_t)n * HH + t];
    float cnt = (float)(end - beg);
    sp[t] = acc / fmaxf(cnt, 1.f);
    __syncthreads();
    float h = fc1b[t];
    #pragma unroll 8
    for (int k = 0; k < HH; k++) h = fmaf(sp[k], fc1W[k * HH + t], h);
    h = fmaxf(h, 0.f);
    float v = h * fc2W[t];
    #pragma unroll
    for (int o = 16; o > 0; o >>= 1) v += __shfl_down_sync(0xffffffffu, v, o);
    if ((t & 31) == 0) sr[t >> 5] = v;
    __syncthreads();
    if (t == 0) out[g] = sr[0] + sr[1] + sr[2] + sr[3] + fc2b[0];
}

// ---------------- launch ----------------
extern "C" void kernel_launch(void* const* d_in, const int* in_sizes, int n_in,
                              void* d_out, int out_size) {
    const float* x    = (const float*)d_in[0];
    const int*   esrc = (const int*)  d_in[1];
    const int*   edst = (const int*)  d_in[2];
    const int*   bids = (const int*)  d_in[3];
    int off = (n_in >= 13) ? 5 : 4;    // num_graphs may or may not be materialized
    const float* W1   = (const float*)d_in[off + 0];
    const float* b1   = (const float*)d_in[off + 1];
    const float* W2   = (const float*)d_in[off + 2];
    const float* b2   = (const float*)d_in[off + 3];
    const float* fc1W = (const float*)d_in[off + 4];
    const float* fc1b = (const float*)d_in[off + 5];
    const float* fc2W = (const float*)d_in[off + 6];
    const float* fc2b = (const float*)d_in[off + 7];
    float* out = (float*)d_out;

    int nb_n  = (NN + 255) / 256;
    int nb_e  = (NE + 255) / 256;
    int nb_nw = (NN * 32 + 255) / 256;

    // graph structure (shared by both layers)
    k_zero<<<nb_n, 256>>>();
    k_hist<<<nb_e, 256>>>(edst, bids);
    k_scan1<<<SCAN_NB, SCAN_BLK>>>();
    k_scan2<<<1, 128>>>();
    k_scan3<<<nb_n, 256>>>(x);
    k_goff<<<1, GG>>>();
    k_fill<<<nb_e, 256>>>(esrc, edst);

    // layer 1 (fused gather-in-input-space + transform + relu)
    k_agg1<<<nb_nw, 256>>>(W1, b1);
    // layer 2
    k_gemm<<<(NN + GTR - 1) / GTR, 256>>>(W2);
    k_agg2<<<nb_nw, 256>>>(b2);
    // pool + head
    k_mlp<<<GG, HH>>>(fc1W, fc1b, fc2W, fc2b, out);
}